// round 9
// baseline (speedup 1.0000x reference)
#include <cuda_runtime.h>
#include <cuda_bf16.h>
#include <cstdint>

// Problem constants
#define B_  256
#define L_  500
#define E_  300
#define H_  10
#define K_  5
#define NKS 19            // k-steps of 16 (covers 304, valid 300)
#define NNT 7             // n-tiles of 8 (56 cols, valid 50)

// global scratch (allowed: __device__ arrays, no runtime allocation)
__device__ uint32_t gBhi[NKS * NNT * 64];
__device__ uint32_t gBlo[NKS * NNT * 64];
__device__ float    gProj[(size_t)B_ * L_ * 50];   // [b][l][kh]

__device__ __forceinline__ uint32_t cvt_bf2(float lo, float hi) {
    uint32_t d;
    asm("cvt.rn.bf16x2.f32 %0, %1, %2;" : "=r"(d) : "f"(hi), "f"(lo));
    return d;
}
__device__ __forceinline__ uint32_t cvt_bf2_lo(float2 v, uint32_t hi) {
    float h0 = __uint_as_float(hi << 16);
    float h1 = __uint_as_float(hi & 0xFFFF0000u);
    return cvt_bf2(v.x - h0, v.y - h1);
}
__device__ __forceinline__ void mma_bf16(float* d, const uint32_t* a,
                                         uint32_t b0, uint32_t b1) {
    asm volatile(
        "mma.sync.aligned.m16n8k16.row.col.f32.bf16.bf16.f32 "
        "{%0,%1,%2,%3}, {%4,%5,%6,%7}, {%8,%9}, {%0,%1,%2,%3};"
        : "+f"(d[0]), "+f"(d[1]), "+f"(d[2]), "+f"(d[3])
        : "r"(a[0]), "r"(a[1]), "r"(a[2]), "r"(a[3]), "r"(b0), "r"(b1));
}

// ---------------- kernel 0: pack B fragments (hi/lo bf16 split) ----------------
__global__ void pack_b_kernel(const float* __restrict__ aspProj) {
    int idx = blockIdx.x * 256 + threadIdx.x;
    if (idx >= NKS * NNT * 64) return;
    int lan = idx & 31;
    int r   = (idx >> 5) & 1;
    int g   = idx >> 6;            // ks*7 + nt
    int nt  = g % NNT, ks = g / NNT;
    int k0  = ks * 16 + ((lan & 3) << 1) + r * 8;
    int n   = nt * 8 + (lan >> 2);
    float w0 = 0.f, w1 = 0.f;
    if (n < 50) {
        int base = (n / H_) * (E_ * H_) + (n % H_);
        if (k0 < E_)     w0 = aspProj[base + k0 * H_];
        if (k0 + 1 < E_) w1 = aspProj[base + (k0 + 1) * H_];
    }
    uint32_t hi = cvt_bf2(w0, w1);
    float h0 = __uint_as_float(hi << 16);
    float h1 = __uint_as_float(hi & 0xFFFF0000u);
    gBhi[idx] = hi;
    gBlo[idx] = cvt_bf2(w0 - h0, w1 - h1);
}

// ---------------- kernel 1: projection GEMM (independent warps, high occ) ------
__global__ __launch_bounds__(256, 3)
void gemm_kernel(const float* __restrict__ review)
{
    const int tid = threadIdx.x, wid = tid >> 5, lane = tid & 31;
    const int b = blockIdx.x >> 2, quarter = blockIdx.x & 3;
    const float* revB = review + (size_t)b * (L_ * E_);
    const int rg = wid >> 1, nh = wid & 1;        // row-group, n-half
    const int ntBase = nh * 4, ntCount = nh ? 3 : 4;
    const int mrow0 = quarter * 128 + rg * 32;
    const int rquad = lane >> 2;                  // 0..7
    const int cpair = (lane & 3) << 1;            // 0,2,4,6

    float acc[2][4][4];
#pragma unroll
    for (int t = 0; t < 2; t++)
#pragma unroll
        for (int j = 0; j < 4; j++)
#pragma unroll
            for (int c = 0; c < 4; c++) acc[t][j][c] = 0.f;

    const float* rowp[4];
#pragma unroll
    for (int t = 0; t < 2; t++) {
        int r0 = mrow0 + t * 16 + rquad;
        int r1 = r0 + 8;
        rowp[t * 2]     = revB + (size_t)((r0 < L_) ? r0 : 0) * E_;
        rowp[t * 2 + 1] = revB + (size_t)((r1 < L_) ? r1 : 0) * E_;
    }

#pragma unroll 1
    for (int ks = 0; ks < NKS; ks++) {
        // B fragments from L2-resident scratch (coalesced 128B per load)
        uint32_t B0h[4], B1h[4], B0l[4], B1l[4];
#pragma unroll
        for (int j = 0; j < 4; j++) if (j < ntCount) {
            int base = ks * (NNT * 64) + (ntBase + j) * 64 + lane;
            B0h[j] = gBhi[base]; B1h[j] = gBhi[base + 32];
            B0l[j] = gBlo[base]; B1l[j] = gBlo[base + 32];
        }
        const int c0 = ks * 16 + cpair;
        const int c1 = c0 + 8;
#pragma unroll
        for (int t = 0; t < 2; t++) {
            const float2 z = make_float2(0.f, 0.f);
            float2 v0 = *reinterpret_cast<const float2*>(rowp[t * 2] + c0);
            float2 v1 = *reinterpret_cast<const float2*>(rowp[t * 2 + 1] + c0);
            float2 v2 = (c1 < E_) ? *reinterpret_cast<const float2*>(rowp[t * 2] + c1) : z;
            float2 v3 = (c1 < E_) ? *reinterpret_cast<const float2*>(rowp[t * 2 + 1] + c1) : z;
            uint32_t ah[4], al[4];
            ah[0] = cvt_bf2(v0.x, v0.y);  al[0] = cvt_bf2_lo(v0, ah[0]);
            ah[1] = cvt_bf2(v1.x, v1.y);  al[1] = cvt_bf2_lo(v1, ah[1]);
            ah[2] = cvt_bf2(v2.x, v2.y);  al[2] = cvt_bf2_lo(v2, ah[2]);
            ah[3] = cvt_bf2(v3.x, v3.y);  al[3] = cvt_bf2_lo(v3, ah[3]);
#pragma unroll
            for (int j = 0; j < 4; j++) if (j < ntCount) {
                mma_bf16(acc[t][j], ah, B0h[j], B1h[j]);   // hi*hi
                mma_bf16(acc[t][j], ah, B0l[j], B1l[j]);   // hi*lo
                mma_bf16(acc[t][j], al, B0h[j], B1h[j]);   // lo*hi
            }
        }
    }

    // writeback -> gProj[b][row][col] (col pairs contiguous, float2 stores)
    float* gP = gProj + (size_t)b * L_ * 50;
#pragma unroll
    for (int t = 0; t < 2; t++) {
        int r0 = mrow0 + t * 16 + rquad;
        int r1 = r0 + 8;
#pragma unroll
        for (int j = 0; j < 4; j++) if (j < ntCount) {
            int col = (ntBase + j) * 8 + cpair;
            if (col < 50) {
                if (r0 < L_)
                    *reinterpret_cast<float2*>(gP + r0 * 50 + col) =
                        make_float2(acc[t][j][0], acc[t][j][1]);
                if (r1 < L_)
                    *reinterpret_cast<float2*>(gP + r1 * 50 + col) =
                        make_float2(acc[t][j][2], acc[t][j][3]);
            }
        }
    }
}

// ---------------- kernel 2: scores + softmax + pooling (per-doc) ---------------
#define SMEM2_FLOATS (L_ * 50 + K_ * L_ + 160)   // 25000 + 2500 + 160
#define SMEM2_BYTES  (SMEM2_FLOATS * 4)          // 110640

__global__ __launch_bounds__(256)
void epi_kernel(const float* __restrict__ aspEmbed, float* __restrict__ out)
{
    extern __shared__ float sm[];
    float* sProj = sm;                  // [l*50 + kh]
    float* sSc   = sm + L_ * 50;        // [k*500 + l]
    float* sAE   = sm + L_ * 50 + K_ * L_;

    const int tid = threadIdx.x, wid = tid >> 5, lane = tid & 31;
    const int b = blockIdx.x;

    const float4* src = reinterpret_cast<const float4*>(gProj + (size_t)b * (L_ * 50));
    for (int i = tid; i < (L_ * 50) / 4; i += 256)
        reinterpret_cast<float4*>(sProj)[i] = src[i];
    for (int i = tid; i < K_ * 3 * H_; i += 256) sAE[i] = aspEmbed[i];
    __syncthreads();

    // window-3 scores
    for (int idx = tid; idx < K_ * L_; idx += 256) {
        int k = idx / L_, l = idx - k * L_;
        const float* aEk = sAE + k * 3 * H_;
        float s = 0.f;
#pragma unroll
        for (int i = 0; i < 3; i++) {
            int ll = l - 1 + i;
            if ((unsigned)ll < (unsigned)L_) {
                const float* pr = sProj + ll * 50 + k * H_;
#pragma unroll
                for (int h = 0; h < H_; h++) s += pr[h] * aEk[h * 3 + i];
            }
        }
        sSc[idx] = s;
    }
    __syncthreads();

    // softmax per k (warp k), write attn (B,K,L)
    if (wid < K_) {
        float* srow = sSc + wid * L_;
        float m = -3.402823466e38f;
        for (int l = lane; l < L_; l += 32) m = fmaxf(m, srow[l]);
#pragma unroll
        for (int o = 16; o > 0; o >>= 1) m = fmaxf(m, __shfl_xor_sync(0xffffffffu, m, o));
        float ssum = 0.f;
        for (int l = lane; l < L_; l += 32) {
            float ev = expf(srow[l] - m);
            srow[l] = ev;
            ssum += ev;
        }
#pragma unroll
        for (int o = 16; o > 0; o >>= 1) ssum += __shfl_xor_sync(0xffffffffu, ssum, o);
        float inv = 1.0f / ssum;
        float* oa = out + (size_t)b * (K_ * L_) + wid * L_;
        for (int l = lane; l < L_; l += 32) {
            float a = srow[l] * inv;
            srow[l] = a;
            oa[l] = a;
        }
    }
    __syncthreads();

    // pooled rep (B,K,H)
    float* orep = out + (size_t)B_ * K_ * L_ + (size_t)b * (K_ * H_);
    for (int kh = wid; kh < K_ * H_; kh += 8) {
        int k = kh / H_;
        const float* ak = sSc + k * L_;
        float s = 0.f;
        for (int l = lane; l < L_; l += 32) s += sProj[l * 50 + kh] * ak[l];
#pragma unroll
        for (int o = 16; o > 0; o >>= 1) s += __shfl_xor_sync(0xffffffffu, s, o);
        if (lane == 0) orep[kh] = s;
    }
}

extern "C" void kernel_launch(void* const* d_in, const int* in_sizes, int n_in,
                              void* d_out, int out_size)
{
    const float* review   = (const float*)d_in[0];
    const float* aspProj  = (const float*)d_in[1];
    const float* aspEmbed = (const float*)d_in[2];
    float* out = (float*)d_out;

    cudaFuncSetAttribute(epi_kernel,
                         cudaFuncAttributeMaxDynamicSharedMemorySize, SMEM2_BYTES);

    pack_b_kernel<<<(NKS * NNT * 64 + 255) / 256, 256>>>(aspProj);
    gemm_kernel<<<B_ * 4, 256>>>(review);
    epi_kernel<<<B_, 256, SMEM2_BYTES>>>(aspEmbed, out);
}

// round 11
// speedup vs baseline: 1.4497x; 1.4497x over previous
#include <cuda_runtime.h>
#include <cuda_bf16.h>
#include <cstdint>

// Problem constants
#define B_  256
#define L_  500
#define E_  300
#define H_  10
#define K_  5

#define NT    1024        // 32 warps: warp w owns rows [w*16, w*16+16)
#define NKS   19          // k-steps of 16 (covers 304, valid 300)
#define NNT   7           // n-tiles of 8 (56 cols, valid 50)

// shared memory layout (bytes)
#define SM_BHI   0
#define SM_BLO   (SM_BHI + NKS*NNT*64*4)     // 34048
#define SM_PROJ  (SM_BLO + NKS*NNT*64*4)     // 68096  (50*500*4 = 100000)
#define SM_SC    (SM_PROJ + 50*500*4)        // 168096 (2500*4 = 10000)
#define SM_AE    (SM_SC + K_*L_*4)           // 178096
#define SMEM_BYTES (SM_AE + 640)             // 178736

__device__ __forceinline__ uint32_t cvt_bf2(float lo, float hi) {
    uint32_t d;
    asm("cvt.rn.bf16x2.f32 %0, %1, %2;" : "=r"(d) : "f"(hi), "f"(lo));
    return d;
}
__device__ __forceinline__ uint32_t cvt_bf2_lo(float2 v, uint32_t hi) {
    float h0 = __uint_as_float(hi << 16);
    float h1 = __uint_as_float(hi & 0xFFFF0000u);
    return cvt_bf2(v.x - h0, v.y - h1);
}
__device__ __forceinline__ void mma_bf16(float* d, const uint32_t* a,
                                         uint32_t b0, uint32_t b1) {
    asm volatile(
        "mma.sync.aligned.m16n8k16.row.col.f32.bf16.bf16.f32 "
        "{%0,%1,%2,%3}, {%4,%5,%6,%7}, {%8,%9}, {%0,%1,%2,%3};"
        : "+f"(d[0]), "+f"(d[1]), "+f"(d[2]), "+f"(d[3])
        : "r"(a[0]), "r"(a[1]), "r"(a[2]), "r"(a[3]), "r"(b0), "r"(b1));
}

__global__ __launch_bounds__(NT, 1)
void anr_arl_kernel(const float* __restrict__ review,
                    const float* __restrict__ aspProj,
                    const float* __restrict__ aspEmbed,
                    float* __restrict__ out)
{
    extern __shared__ char smc[];
    uint32_t* sBhi   = reinterpret_cast<uint32_t*>(smc + SM_BHI);
    uint32_t* sBlo   = reinterpret_cast<uint32_t*>(smc + SM_BLO);
    float*    sProj  = reinterpret_cast<float*>(smc + SM_PROJ);   // [kh*500 + l]
    float*    sScores= reinterpret_cast<float*>(smc + SM_SC);     // [k*500 + l]
    float*    sAE    = reinterpret_cast<float*>(smc + SM_AE);

    const int tid  = threadIdx.x;
    const int wid  = tid >> 5, lane = tid & 31;
    const int b    = blockIdx.x;
    const float* revB = review + (size_t)b * (L_ * E_);

    // ---- stage B fragments: [ks][nt][r][lane] u32 = bf16 pair (k0, k0+1) ----
    // B[k][n] = aspProj[n/10, k, n%10]; hi = bf16(w), lo = bf16(w - hi)
    for (int idx = tid; idx < NKS * NNT * 64; idx += NT) {
        int lan = idx & 31;
        int r   = (idx >> 5) & 1;
        int g   = idx >> 6;                // ks*7 + nt
        int nt  = g % NNT, ks = g / NNT;
        int k0  = ks * 16 + ((lan & 3) << 1) + r * 8;
        int n   = nt * 8 + (lan >> 2);
        float w0 = 0.f, w1 = 0.f;
        if (n < 50) {
            int base = (n / H_) * (E_ * H_) + (n % H_);
            if (k0 < E_)     w0 = aspProj[base + k0 * H_];
            if (k0 + 1 < E_) w1 = aspProj[base + (k0 + 1) * H_];
        }
        uint32_t hi = cvt_bf2(w0, w1);
        float h0 = __uint_as_float(hi << 16);
        float h1 = __uint_as_float(hi & 0xFFFF0000u);
        uint32_t lo = cvt_bf2(w0 - h0, w1 - h1);
        sBhi[idx] = hi;
        sBlo[idx] = lo;
    }
    for (int i = tid; i < K_ * 3 * H_; i += NT) sAE[i] = aspEmbed[i];
    __syncthreads();

    // ---- GEMM mainloop: warp w owns ONE 16-row m-tile, all 7 n-tiles ----
    float acc[NNT][4];
#pragma unroll
    for (int nt = 0; nt < NNT; nt++)
#pragma unroll
        for (int c = 0; c < 4; c++) acc[nt][c] = 0.f;

    const int mrow0 = wid * 16;           // 0..496 (wid 31 covers 496..511; >=500 discarded)
    const int rquad = lane >> 2;          // 0..7
    const int cpair = (lane & 3) << 1;    // 0,2,4,6

    const int r0 = mrow0 + rquad;
    const int r1 = r0 + 8;
    const float* rowp0 = revB + (size_t)((r0 < L_) ? r0 : 0) * E_;
    const float* rowp1 = revB + (size_t)((r1 < L_) ? r1 : 0) * E_;

#pragma unroll 1
    for (int ks = 0; ks < NKS; ks++) {
        const int c0 = ks * 16 + cpair;   // <= 294, always valid
        const int c1 = c0 + 8;            // may exceed 299 on last step
        const float2 z = make_float2(0.f, 0.f);
        float2 v0 = *reinterpret_cast<const float2*>(rowp0 + c0);
        float2 v1 = *reinterpret_cast<const float2*>(rowp1 + c0);
        float2 v2 = (c1 < E_) ? *reinterpret_cast<const float2*>(rowp0 + c1) : z;
        float2 v3 = (c1 < E_) ? *reinterpret_cast<const float2*>(rowp1 + c1) : z;

        uint32_t ah[4], al[4];
        ah[0] = cvt_bf2(v0.x, v0.y);  al[0] = cvt_bf2_lo(v0, ah[0]);
        ah[1] = cvt_bf2(v1.x, v1.y);  al[1] = cvt_bf2_lo(v1, ah[1]);
        ah[2] = cvt_bf2(v2.x, v2.y);  al[2] = cvt_bf2_lo(v2, ah[2]);
        ah[3] = cvt_bf2(v3.x, v3.y);  al[3] = cvt_bf2_lo(v3, ah[3]);

        const uint32_t* bh = sBhi + ks * (NNT * 64);
        const uint32_t* bl = sBlo + ks * (NNT * 64);
#pragma unroll
        for (int nt = 0; nt < NNT; nt++) {
            uint32_t b0h = bh[(nt * 2 + 0) * 32 + lane];
            uint32_t b1h = bh[(nt * 2 + 1) * 32 + lane];
            uint32_t b0l = bl[(nt * 2 + 0) * 32 + lane];
            uint32_t b1l = bl[(nt * 2 + 1) * 32 + lane];
            mma_bf16(acc[nt], ah, b0h, b1h);   // hi*hi
            mma_bf16(acc[nt], ah, b0l, b1l);   // hi*lo
            mma_bf16(acc[nt], al, b0h, b1h);   // lo*hi
        }
    }

    // ---- writeback acc -> sProj[kh][l] ----
#pragma unroll
    for (int nt = 0; nt < NNT; nt++) {
#pragma unroll
        for (int c = 0; c < 4; c++) {
            int row = mrow0 + rquad + ((c >> 1) ? 8 : 0);
            int col = nt * 8 + cpair + (c & 1);
            if (row < L_ && col < 50)
                sProj[col * L_ + row] = acc[nt][c];
        }
    }
    __syncthreads();

    // ---- window-3 attention scores: scores[k][l] ----
    for (int idx = tid; idx < K_ * L_; idx += NT) {
        int k = idx / L_, l = idx - k * L_;
        const float* aEk = sAE + k * 3 * H_;
        const float* pk  = sProj + k * H_ * L_;
        float s = 0.f;
#pragma unroll
        for (int i = 0; i < 3; i++) {
            int ll = l - 1 + i;
            if ((unsigned)ll < (unsigned)L_) {
#pragma unroll
                for (int h = 0; h < H_; h++)
                    s += pk[h * L_ + ll] * aEk[h * 3 + i];
            }
        }
        sScores[idx] = s;
    }
    __syncthreads();

    // ---- softmax over l per k (warp k), write attn out (B,K,L) ----
    if (wid < K_) {
        float* srow = sScores + wid * L_;
        float m = -3.402823466e38f;
        for (int l = lane; l < L_; l += 32) m = fmaxf(m, srow[l]);
#pragma unroll
        for (int o = 16; o > 0; o >>= 1) m = fmaxf(m, __shfl_xor_sync(0xffffffffu, m, o));
        float ssum = 0.f;
        for (int l = lane; l < L_; l += 32) {
            float ev = expf(srow[l] - m);
            srow[l] = ev;
            ssum += ev;
        }
#pragma unroll
        for (int o = 16; o > 0; o >>= 1) ssum += __shfl_xor_sync(0xffffffffu, ssum, o);
        float inv = 1.0f / ssum;
        float* oa = out + (size_t)b * (K_ * L_) + wid * L_;
        for (int l = lane; l < L_; l += 32) {
            float a = srow[l] * inv;
            srow[l] = a;          // keep normalized attn for pooling
            oa[l] = a;
        }
    }
    __syncthreads();

    // ---- pooled rep: rep[k][h] = sum_l proj[kh][l] * attn[k][l]  -> (B,K,H) ----
    float* orep = out + (size_t)B_ * K_ * L_ + (size_t)b * (K_ * H_);
    for (int kh = wid; kh < K_ * H_; kh += (NT / 32)) {
        int k = kh / H_;
        const float* pk = sProj + kh * L_;
        const float* ak = sScores + k * L_;
        float s = 0.f;
        for (int l = lane; l < L_; l += 32) s += pk[l] * ak[l];
#pragma unroll
        for (int o = 16; o > 0; o >>= 1) s += __shfl_xor_sync(0xffffffffu, s, o);
        if (lane == 0) orep[kh] = s;
    }
}

extern "C" void kernel_launch(void* const* d_in, const int* in_sizes, int n_in,
                              void* d_out, int out_size)
{
    const float* review   = (const float*)d_in[0];
    const float* aspProj  = (const float*)d_in[1];
    const float* aspEmbed = (const float*)d_in[2];
    float* out = (float*)d_out;

    cudaFuncSetAttribute(anr_arl_kernel,
                         cudaFuncAttributeMaxDynamicSharedMemorySize, SMEM_BYTES);
    anr_arl_kernel<<<B_, NT, SMEM_BYTES>>>(review, aspProj, aspEmbed, out);
}

// round 13
// speedup vs baseline: 1.5399x; 1.0623x over previous
#include <cuda_runtime.h>
#include <cuda_bf16.h>
#include <cstdint>

// Problem constants
#define B_  256
#define L_  500
#define E_  300
#define H_  10
#define K_  5

#define NT    1024        // 32 warps: warp w owns rows [w*16, w*16+16)
#define NKS   19          // k-steps of 16 (covers 304, valid 300)
#define NNT   7           // n-tiles of 8 (56 cols, valid 50)

// shared memory layout (bytes)
// B fragments: [ks][nt][lane] uint4 {b0h, b1h, b0l, b1l} -> 19*7*32*16 = 68096
#define SM_B     0
#define SM_PROJ  (NKS*NNT*32*16)             // 68096  (50*500*4 = 100000)
#define SM_SC    (SM_PROJ + 50*500*4)        // 168096 (2500*4 = 10000)
#define SM_AE    (SM_SC + K_*L_*4)           // 178096
#define SMEM_BYTES (SM_AE + 640)             // 178736

__device__ __forceinline__ uint32_t cvt_bf2(float lo, float hi) {
    uint32_t d;
    asm("cvt.rn.bf16x2.f32 %0, %1, %2;" : "=r"(d) : "f"(hi), "f"(lo));
    return d;
}
__device__ __forceinline__ uint32_t cvt_bf2_lo(float2 v, uint32_t hi) {
    float h0 = __uint_as_float(hi << 16);
    float h1 = __uint_as_float(hi & 0xFFFF0000u);
    return cvt_bf2(v.x - h0, v.y - h1);
}
__device__ __forceinline__ void mma_bf16(float* d, const uint32_t* a,
                                         uint32_t b0, uint32_t b1) {
    asm volatile(
        "mma.sync.aligned.m16n8k16.row.col.f32.bf16.bf16.f32 "
        "{%0,%1,%2,%3}, {%4,%5,%6,%7}, {%8,%9}, {%0,%1,%2,%3};"
        : "+f"(d[0]), "+f"(d[1]), "+f"(d[2]), "+f"(d[3])
        : "r"(a[0]), "r"(a[1]), "r"(a[2]), "r"(a[3]), "r"(b0), "r"(b1));
}

__global__ __launch_bounds__(NT, 1)
void anr_arl_kernel(const float* __restrict__ review,
                    const float* __restrict__ aspProj,
                    const float* __restrict__ aspEmbed,
                    float* __restrict__ out)
{
    extern __shared__ char smc[];
    uint4*  sB      = reinterpret_cast<uint4*>(smc + SM_B);
    float*  sProj   = reinterpret_cast<float*>(smc + SM_PROJ);   // [kh*500 + l]
    float*  sScores = reinterpret_cast<float*>(smc + SM_SC);     // [k*500 + l]
    float*  sAE     = reinterpret_cast<float*>(smc + SM_AE);

    const int tid  = threadIdx.x;
    const int wid  = tid >> 5, lane = tid & 31;
    const int b    = blockIdx.x;
    const float* revB = review + (size_t)b * (L_ * E_);

    // ---- stage B fragments: per (ks, nt, lane): uint4 {b0h, b1h, b0l, b1l} ----
    // B[k][n] = aspProj[n/10, k, n%10]; hi = bf16(w), lo = bf16(w - hi)
    // b0 covers k-offsets {0..7} of the step, b1 covers {8..15}
    for (int idx = tid; idx < NKS * NNT * 32; idx += NT) {
        int lan = idx & 31;
        int g   = idx >> 5;                // ks*NNT + nt
        int nt  = g % NNT, ks = g / NNT;
        int n   = nt * 8 + (lan >> 2);
        int kb  = ks * 16 + ((lan & 3) << 1);
        float w[4] = {0.f, 0.f, 0.f, 0.f};   // {k, k+1, k+8, k+9}
        if (n < 50) {
            int base = (n / H_) * (E_ * H_) + (n % H_);
            if (kb < E_)     w[0] = aspProj[base + kb * H_];
            if (kb + 1 < E_) w[1] = aspProj[base + (kb + 1) * H_];
            if (kb + 8 < E_) w[2] = aspProj[base + (kb + 8) * H_];
            if (kb + 9 < E_) w[3] = aspProj[base + (kb + 9) * H_];
        }
        uint4 val;
        val.x = cvt_bf2(w[0], w[1]);   // b0h
        val.y = cvt_bf2(w[2], w[3]);   // b1h
        float h0 = __uint_as_float(val.x << 16);
        float h1 = __uint_as_float(val.x & 0xFFFF0000u);
        float h2 = __uint_as_float(val.y << 16);
        float h3 = __uint_as_float(val.y & 0xFFFF0000u);
        val.z = cvt_bf2(w[0] - h0, w[1] - h1);   // b0l
        val.w = cvt_bf2(w[2] - h2, w[3] - h3);   // b1l
        sB[idx] = val;
    }
    for (int i = tid; i < K_ * 3 * H_; i += NT) sAE[i] = aspEmbed[i];
    __syncthreads();

    // ---- GEMM mainloop: warp w owns ONE 16-row m-tile, all 7 n-tiles ----
    float acc[NNT][4];
#pragma unroll
    for (int nt = 0; nt < NNT; nt++)
#pragma unroll
        for (int c = 0; c < 4; c++) acc[nt][c] = 0.f;

    const int mrow0 = wid * 16;           // 0..496 (rows >= 500 computed, discarded)
    const int rquad = lane >> 2;          // 0..7
    const int cpair = (lane & 3) << 1;    // 0,2,4,6

    const int r0 = mrow0 + rquad;
    const int r1 = r0 + 8;
    const float* rowp0 = revB + (size_t)((r0 < L_) ? r0 : 0) * E_;
    const float* rowp1 = revB + (size_t)((r1 < L_) ? r1 : 0) * E_;

#pragma unroll 1
    for (int ks = 0; ks < NKS; ks++) {
        const int c0 = ks * 16 + cpair;   // <= 294, always valid
        const int c1 = c0 + 8;            // may exceed 299 on last step
        const float2 z = make_float2(0.f, 0.f);
        float2 v0 = *reinterpret_cast<const float2*>(rowp0 + c0);
        float2 v1 = *reinterpret_cast<const float2*>(rowp1 + c0);
        float2 v2 = (c1 < E_) ? *reinterpret_cast<const float2*>(rowp0 + c1) : z;
        float2 v3 = (c1 < E_) ? *reinterpret_cast<const float2*>(rowp1 + c1) : z;

        uint32_t ah[4], al[4];
        ah[0] = cvt_bf2(v0.x, v0.y);  al[0] = cvt_bf2_lo(v0, ah[0]);
        ah[1] = cvt_bf2(v1.x, v1.y);  al[1] = cvt_bf2_lo(v1, ah[1]);
        ah[2] = cvt_bf2(v2.x, v2.y);  al[2] = cvt_bf2_lo(v2, ah[2]);
        ah[3] = cvt_bf2(v3.x, v3.y);  al[3] = cvt_bf2_lo(v3, ah[3]);

        const uint4* bp = sB + ks * (NNT * 32) + lane;
#pragma unroll
        for (int nt = 0; nt < NNT; nt++) {
            uint4 f = bp[nt * 32];           // single LDS.128: {b0h,b1h,b0l,b1l}
            mma_bf16(acc[nt], ah, f.x, f.y);   // hi*hi
            mma_bf16(acc[nt], ah, f.z, f.w);   // hi*lo
            mma_bf16(acc[nt], al, f.x, f.y);   // lo*hi
        }
    }

    // ---- writeback acc -> sProj[kh][l] ----
#pragma unroll
    for (int nt = 0; nt < NNT; nt++) {
#pragma unroll
        for (int c = 0; c < 4; c++) {
            int row = mrow0 + rquad + ((c >> 1) ? 8 : 0);
            int col = nt * 8 + cpair + (c & 1);
            if (row < L_ && col < 50)
                sProj[col * L_ + row] = acc[nt][c];
        }
    }
    __syncthreads();

    // ---- window-3 attention scores: scores[k][l] ----
    for (int idx = tid; idx < K_ * L_; idx += NT) {
        int k = idx / L_, l = idx - k * L_;
        const float* aEk = sAE + k * 3 * H_;
        const float* pk  = sProj + k * H_ * L_;
        float s = 0.f;
#pragma unroll
        for (int i = 0; i < 3; i++) {
            int ll = l - 1 + i;
            if ((unsigned)ll < (unsigned)L_) {
#pragma unroll
                for (int h = 0; h < H_; h++)
                    s += pk[h * L_ + ll] * aEk[h * 3 + i];
            }
        }
        sScores[idx] = s;
    }
    __syncthreads();

    // ---- softmax over l per k (warp k), write attn out (B,K,L) ----
    if (wid < K_) {
        float* srow = sScores + wid * L_;
        float m = -3.402823466e38f;
        for (int l = lane; l < L_; l += 32) m = fmaxf(m, srow[l]);
#pragma unroll
        for (int o = 16; o > 0; o >>= 1) m = fmaxf(m, __shfl_xor_sync(0xffffffffu, m, o));
        float ssum = 0.f;
        for (int l = lane; l < L_; l += 32) {
            float ev = expf(srow[l] - m);
            srow[l] = ev;
            ssum += ev;
        }
#pragma unroll
        for (int o = 16; o > 0; o >>= 1) ssum += __shfl_xor_sync(0xffffffffu, ssum, o);
        float inv = 1.0f / ssum;
        float* oa = out + (size_t)b * (K_ * L_) + wid * L_;
        for (int l = lane; l < L_; l += 32) {
            float a = srow[l] * inv;
            srow[l] = a;          // keep normalized attn for pooling
            oa[l] = a;
        }
    }
    __syncthreads();

    // ---- pooled rep: rep[k][h] = sum_l proj[kh][l] * attn[k][l]  -> (B,K,H) ----
    float* orep = out + (size_t)B_ * K_ * L_ + (size_t)b * (K_ * H_);
    for (int kh = wid; kh < K_ * H_; kh += (NT / 32)) {
        int k = kh / H_;
        const float* pk = sProj + kh * L_;
        const float* ak = sScores + k * L_;
        float s = 0.f;
        for (int l = lane; l < L_; l += 32) s += pk[l] * ak[l];
#pragma unroll
        for (int o = 16; o > 0; o >>= 1) s += __shfl_xor_sync(0xffffffffu, s, o);
        if (lane == 0) orep[kh] = s;
    }
}

extern "C" void kernel_launch(void* const* d_in, const int* in_sizes, int n_in,
                              void* d_out, int out_size)
{
    const float* review   = (const float*)d_in[0];
    const float* aspProj  = (const float*)d_in[1];
    const float* aspEmbed = (const float*)d_in[2];
    float* out = (float*)d_out;

    cudaFuncSetAttribute(anr_arl_kernel,
                         cudaFuncAttributeMaxDynamicSharedMemorySize, SMEM_BYTES);
    anr_arl_kernel<<<B_, NT, SMEM_BYTES>>>(review, aspProj, aspEmbed, out);
}

// round 14
// speedup vs baseline: 1.9161x; 1.2443x over previous
#include <cuda_runtime.h>
#include <cuda_fp16.h>
#include <cstdint>

// Problem constants
#define B_  256
#define L_  500
#define E_  300
#define H_  10
#define K_  5

#define NT    1024        // 32 warps: warp w owns rows [w*16, w*16+16)
#define NKS   19          // k-steps of 16 (covers 304, valid 300)
#define NNT   7           // n-tiles of 8 (56 cols, valid 50)

// shared memory layout (bytes)
// B fragments (fp16 hi only): [ks][nt][lane] uint2 {b0h, b1h} -> 19*7*32*8 = 34048
#define SM_B     0
#define SM_PROJ  (NKS*NNT*32*8)              // 34048  (50*500*4 = 100000)
#define SM_SC    (SM_PROJ + 50*500*4)        // 134048 (2500*4 = 10000)
#define SM_AE    (SM_SC + K_*L_*4)           // 144048
#define SMEM_BYTES (SM_AE + 640)             // 144688

__device__ __forceinline__ uint32_t cvt_h2(float lo, float hi) {
    uint32_t d;
    asm("cvt.rn.f16x2.f32 %0, %1, %2;" : "=r"(d) : "f"(hi), "f"(lo));
    return d;
}
__device__ __forceinline__ float2 unpack_h2(uint32_t h) {
    float2 r;
    asm("{\n\t.reg .f16 l, hh;\n\t"
        "mov.b32 {l, hh}, %2;\n\t"
        "cvt.f32.f16 %0, l;\n\t"
        "cvt.f32.f16 %1, hh;\n\t}"
        : "=f"(r.x), "=f"(r.y) : "r"(h));
    return r;
}
// residual pair after removing fp16 hi parts
__device__ __forceinline__ uint32_t cvt_h2_lo(float2 v, uint32_t hi) {
    float2 h = unpack_h2(hi);
    return cvt_h2(v.x - h.x, v.y - h.y);
}
__device__ __forceinline__ void mma_f16(float* d, const uint32_t* a,
                                        uint32_t b0, uint32_t b1) {
    asm volatile(
        "mma.sync.aligned.m16n8k16.row.col.f32.f16.f16.f32 "
        "{%0,%1,%2,%3}, {%4,%5,%6,%7}, {%8,%9}, {%0,%1,%2,%3};"
        : "+f"(d[0]), "+f"(d[1]), "+f"(d[2]), "+f"(d[3])
        : "r"(a[0]), "r"(a[1]), "r"(a[2]), "r"(a[3]), "r"(b0), "r"(b1));
}

__global__ __launch_bounds__(NT, 1)
void anr_arl_kernel(const float* __restrict__ review,
                    const float* __restrict__ aspProj,
                    const float* __restrict__ aspEmbed,
                    float* __restrict__ out)
{
    extern __shared__ char smc[];
    uint2*  sB      = reinterpret_cast<uint2*>(smc + SM_B);
    float*  sProj   = reinterpret_cast<float*>(smc + SM_PROJ);   // [kh*500 + l]
    float*  sScores = reinterpret_cast<float*>(smc + SM_SC);     // [k*500 + l]
    float*  sAE     = reinterpret_cast<float*>(smc + SM_AE);

    const int tid  = threadIdx.x;
    const int wid  = tid >> 5, lane = tid & 31;
    const int b    = blockIdx.x;
    const float* revB = review + (size_t)b * (L_ * E_);

    // ---- stage B fragments (fp16 hi only): per (ks, nt, lane): uint2 {b0h, b1h} ----
    // B[k][n] = aspProj[n/10, k, n%10]
    // b0 covers k-offsets {0..7} of the step, b1 covers {8..15}
    for (int idx = tid; idx < NKS * NNT * 32; idx += NT) {
        int lan = idx & 31;
        int g   = idx >> 5;                // ks*NNT + nt
        int nt  = g % NNT, ks = g / NNT;
        int n   = nt * 8 + (lan >> 2);
        int kb  = ks * 16 + ((lan & 3) << 1);
        float w[4] = {0.f, 0.f, 0.f, 0.f};   // {k, k+1, k+8, k+9}
        if (n < 50) {
            int base = (n / H_) * (E_ * H_) + (n % H_);
            if (kb < E_)     w[0] = aspProj[base + kb * H_];
            if (kb + 1 < E_) w[1] = aspProj[base + (kb + 1) * H_];
            if (kb + 8 < E_) w[2] = aspProj[base + (kb + 8) * H_];
            if (kb + 9 < E_) w[3] = aspProj[base + (kb + 9) * H_];
        }
        uint2 val;
        val.x = cvt_h2(w[0], w[1]);
        val.y = cvt_h2(w[2], w[3]);
        sB[idx] = val;
    }
    for (int i = tid; i < K_ * 3 * H_; i += NT) sAE[i] = aspEmbed[i];
    __syncthreads();

    // ---- GEMM mainloop: warp w owns ONE 16-row m-tile, all 7 n-tiles ----
    // D = A*B computed as ah*bh + al*bh (fp16 split of A; B fp16-rounded)
    float acc[NNT][4];
#pragma unroll
    for (int nt = 0; nt < NNT; nt++)
#pragma unroll
        for (int c = 0; c < 4; c++) acc[nt][c] = 0.f;

    const int mrow0 = wid * 16;           // 0..496 (rows >= 500 computed, discarded)
    const int rquad = lane >> 2;          // 0..7
    const int cpair = (lane & 3) << 1;    // 0,2,4,6

    const int r0 = mrow0 + rquad;
    const int r1 = r0 + 8;
    const float* rowp0 = revB + (size_t)((r0 < L_) ? r0 : 0) * E_;
    const float* rowp1 = revB + (size_t)((r1 < L_) ? r1 : 0) * E_;

#pragma unroll 1
    for (int ks = 0; ks < NKS; ks++) {
        const int c0 = ks * 16 + cpair;   // <= 294, always valid
        const int c1 = c0 + 8;            // may exceed 299 on last step
        const float2 z = make_float2(0.f, 0.f);
        float2 v0 = *reinterpret_cast<const float2*>(rowp0 + c0);
        float2 v1 = *reinterpret_cast<const float2*>(rowp1 + c0);
        float2 v2 = (c1 < E_) ? *reinterpret_cast<const float2*>(rowp0 + c1) : z;
        float2 v3 = (c1 < E_) ? *reinterpret_cast<const float2*>(rowp1 + c1) : z;

        uint32_t ah[4], al[4];
        ah[0] = cvt_h2(v0.x, v0.y);  al[0] = cvt_h2_lo(v0, ah[0]);
        ah[1] = cvt_h2(v1.x, v1.y);  al[1] = cvt_h2_lo(v1, ah[1]);
        ah[2] = cvt_h2(v2.x, v2.y);  al[2] = cvt_h2_lo(v2, ah[2]);
        ah[3] = cvt_h2(v3.x, v3.y);  al[3] = cvt_h2_lo(v3, ah[3]);

        const uint2* bp = sB + ks * (NNT * 32) + lane;
        uint2 fn = bp[0];                  // rotating B prefetch
#pragma unroll
        for (int nt = 0; nt < NNT; nt++) {
            uint2 f = fn;
            if (nt + 1 < NNT) fn = bp[(nt + 1) * 32];
            mma_f16(acc[nt], ah, f.x, f.y);   // hi * hi
            mma_f16(acc[nt], al, f.x, f.y);   // lo * hi
        }
    }

    // ---- writeback acc -> sProj[kh][l] ----
#pragma unroll
    for (int nt = 0; nt < NNT; nt++) {
#pragma unroll
        for (int c = 0; c < 4; c++) {
            int row = mrow0 + rquad + ((c >> 1) ? 8 : 0);
            int col = nt * 8 + cpair + (c & 1);
            if (row < L_ && col < 50)
                sProj[col * L_ + row] = acc[nt][c];
        }
    }
    __syncthreads();

    // ---- window-3 attention scores: scores[k][l] ----
    for (int idx = tid; idx < K_ * L_; idx += NT) {
        int k = idx / L_, l = idx - k * L_;
        const float* aEk = sAE + k * 3 * H_;
        const float* pk  = sProj + k * H_ * L_;
        float s = 0.f;
#pragma unroll
        for (int i = 0; i < 3; i++) {
            int ll = l - 1 + i;
            if ((unsigned)ll < (unsigned)L_) {
#pragma unroll
                for (int h = 0; h < H_; h++)
                    s += pk[h * L_ + ll] * aEk[h * 3 + i];
            }
        }
        sScores[idx] = s;
    }
    __syncthreads();

    // ---- softmax over l per k (warp k), write attn out (B,K,L) ----
    if (wid < K_) {
        float* srow = sScores + wid * L_;
        float m = -3.402823466e38f;
        for (int l = lane; l < L_; l += 32) m = fmaxf(m, srow[l]);
#pragma unroll
        for (int o = 16; o > 0; o >>= 1) m = fmaxf(m, __shfl_xor_sync(0xffffffffu, m, o));
        float ssum = 0.f;
        for (int l = lane; l < L_; l += 32) {
            float ev = expf(srow[l] - m);
            srow[l] = ev;
            ssum += ev;
        }
#pragma unroll
        for (int o = 16; o > 0; o >>= 1) ssum += __shfl_xor_sync(0xffffffffu, ssum, o);
        float inv = 1.0f / ssum;
        float* oa = out + (size_t)b * (K_ * L_) + wid * L_;
        for (int l = lane; l < L_; l += 32) {
            float a = srow[l] * inv;
            srow[l] = a;          // keep normalized attn for pooling
            oa[l] = a;
        }
    }
    __syncthreads();

    // ---- pooled rep: rep[k][h] = sum_l proj[kh][l] * attn[k][l]  -> (B,K,H) ----
    float* orep = out + (size_t)B_ * K_ * L_ + (size_t)b * (K_ * H_);
    for (int kh = wid; kh < K_ * H_; kh += (NT / 32)) {
        int k = kh / H_;
        const float* pk = sProj + kh * L_;
        const float* ak = sScores + k * L_;
        float s = 0.f;
        for (int l = lane; l < L_; l += 32) s += pk[l] * ak[l];
#pragma unroll
        for (int o = 16; o > 0; o >>= 1) s += __shfl_xor_sync(0xffffffffu, s, o);
        if (lane == 0) orep[kh] = s;
    }
}

extern "C" void kernel_launch(void* const* d_in, const int* in_sizes, int n_in,
                              void* d_out, int out_size)
{
    const float* review   = (const float*)d_in[0];
    const float* aspProj  = (const float*)d_in[1];
    const float* aspEmbed = (const float*)d_in[2];
    float* out = (float*)d_out;

    cudaFuncSetAttribute(anr_arl_kernel,
                         cudaFuncAttributeMaxDynamicSharedMemorySize, SMEM_BYTES);
    anr_arl_kernel<<<B_, NT, SMEM_BYTES>>>(review, aspProj, aspEmbed, out);
}

// round 17
// speedup vs baseline: 2.0474x; 1.0685x over previous
#include <cuda_runtime.h>
#include <cuda_fp16.h>
#include <cstdint>

// Problem constants
#define B_  256
#define L_  500
#define E_  300
#define H_  10
#define K_  5

#define NT    1024        // 32 warps: warp w owns rows [w*16, w*16+16)
#define NKS   19          // k-steps of 16 (covers 304, valid 300)
#define NNT   7           // n-tiles of 8 (56 cols, valid 50)
#define DEPTH 4           // per-warp A-stage ring depth

// shared memory layout (bytes)
// A ring: per warp DEPTH slots x 1024 B (16 rows x 64 B) -> 32*4*1024 = 131072
#define SM_A     0
#define SM_B     (32 * DEPTH * 1024)          // 131072; B frags 19*7*32*8 = 34048
#define SM_AE    (SM_B + NKS*NNT*32*8)        // 165120
#define SMEM_BYTES (SM_AE + 640)              // 165760
// epilogue aliases (A ring dead after mainloop + syncthreads)
#define SM_PROJ  0                            // 50*500*4 = 100000
#define SM_SC    (50*L_*4)                    // 100000..110000

__device__ __forceinline__ uint32_t cvt_h2(float lo, float hi) {
    uint32_t d;
    asm("cvt.rn.f16x2.f32 %0, %1, %2;" : "=r"(d) : "f"(hi), "f"(lo));
    return d;
}
__device__ __forceinline__ float2 unpack_h2(uint32_t h) {
    float2 r;
    asm("{\n\t.reg .f16 l, hh;\n\t"
        "mov.b32 {l, hh}, %2;\n\t"
        "cvt.f32.f16 %0, l;\n\t"
        "cvt.f32.f16 %1, hh;\n\t}"
        : "=f"(r.x), "=f"(r.y) : "r"(h));
    return r;
}
__device__ __forceinline__ uint32_t cvt_h2_lo(float x, float y, uint32_t hi) {
    float2 h = unpack_h2(hi);
    return cvt_h2(x - h.x, y - h.y);
}
__device__ __forceinline__ void mma_f16(float* d, const uint32_t* a,
                                        uint32_t b0, uint32_t b1) {
    asm volatile(
        "mma.sync.aligned.m16n8k16.row.col.f32.f16.f16.f32 "
        "{%0,%1,%2,%3}, {%4,%5,%6,%7}, {%8,%9}, {%0,%1,%2,%3};"
        : "+f"(d[0]), "+f"(d[1]), "+f"(d[2]), "+f"(d[3])
        : "r"(a[0]), "r"(a[1]), "r"(a[2]), "r"(a[3]), "r"(b0), "r"(b1));
}

__global__ __launch_bounds__(NT, 1)
void anr_arl_kernel(const float* __restrict__ review,
                    const float* __restrict__ aspProj,
                    const float* __restrict__ aspEmbed,
                    float* __restrict__ out)
{
    extern __shared__ char smc[];
    uint2*  sB      = reinterpret_cast<uint2*>(smc + SM_B);
    float*  sAE     = reinterpret_cast<float*>(smc + SM_AE);
    float*  sProj   = reinterpret_cast<float*>(smc + SM_PROJ);   // alias A ring
    float*  sScores = reinterpret_cast<float*>(smc + SM_SC);     // alias A ring

    const int tid  = threadIdx.x;
    const int wid  = tid >> 5, lane = tid & 31;
    const int b    = blockIdx.x;
    const float* revB = review + (size_t)b * (L_ * E_);

    const int mrow0 = wid * 16;
    const int rquad = lane >> 2;          // 0..7
    const int q4    = (lane & 3) << 2;    // 0,4,8,12  (k-remap: lane owns cols 4q..4q+3)

    // per-lane staging sources (rows fixed; rows >= 500 clamped to 0, outputs discarded)
    const int r0 = mrow0 + rquad, r1 = r0 + 8;
    const float* srcB0 = revB + (size_t)((r0 < L_) ? r0 : 0) * E_ + q4;
    const float* srcB1 = revB + (size_t)((r1 < L_) ? r1 : 0) * E_ + q4;
    const unsigned slotBase = (unsigned)__cvta_generic_to_shared(smc)
                            + (unsigned)(wid * (DEPTH * 1024));

    // stage k-step ks into ring slot ks%DEPTH; each lane writes ONLY the two
    // 16B chunks it will itself read back (chunk idx = lane and lane+32)
    auto stageA = [&](int ks) {
        unsigned dst = slotBase + (unsigned)((ks & (DEPTH - 1)) << 10)
                     + (unsigned)(lane << 4);
        const float* s0 = srcB0 + ks * 16;
        const float* s1 = srcB1 + ks * 16;
        if (ks * 16 + q4 + 3 < E_) {
            asm volatile("cp.async.cg.shared.global [%0], [%1], 16;" :: "r"(dst), "l"(s0) : "memory");
            asm volatile("cp.async.cg.shared.global [%0], [%1], 16;" :: "r"(dst + 512), "l"(s1) : "memory");
        } else {   // k-cols >= 300 (only ks=18, q4=12): zero-fill
            asm volatile("st.shared.v4.b32 [%0], {%1,%1,%1,%1};" :: "r"(dst), "r"(0) : "memory");
            asm volatile("st.shared.v4.b32 [%0], {%1,%1,%1,%1};" :: "r"(dst + 512), "r"(0) : "memory");
        }
        asm volatile("cp.async.commit_group;" ::: "memory");
    };

    // kick off the ring early
    stageA(0); stageA(1); stageA(2);

    // ---- stage B fragments (fp16, k-remapped): per (ks,nt,lane) uint2 {b0,b1} ----
    // fragment k-positions {2q,2q+1} <- global k {4q,4q+1}; {8+2q,8+2q+1} <- {4q+2,4q+3}
    for (int idx = tid; idx < NKS * NNT * 32; idx += NT) {
        int lan = idx & 31;
        int g   = idx >> 5;                // ks*NNT + nt
        int nt  = g % NNT, ks = g / NNT;
        int n   = nt * 8 + (lan >> 2);
        int kb  = ks * 16 + ((lan & 3) << 2);
        float w[4] = {0.f, 0.f, 0.f, 0.f};
        if (n < 50) {
            int base = (n / H_) * (E_ * H_) + (n % H_);
#pragma unroll
            for (int i = 0; i < 4; i++)
                if (kb + i < E_) w[i] = aspProj[base + (kb + i) * H_];
        }
        uint2 val;
        val.x = cvt_h2(w[0], w[1]);
        val.y = cvt_h2(w[2], w[3]);
        sB[idx] = val;
    }
    for (int i = tid; i < K_ * 3 * H_; i += NT) sAE[i] = aspEmbed[i];
    __syncthreads();

    // ---- GEMM mainloop: per-warp cp.async ring, no block syncs ----
    float acc[NNT][4];
#pragma unroll
    for (int nt = 0; nt < NNT; nt++)
#pragma unroll
        for (int c = 0; c < 4; c++) acc[nt][c] = 0.f;

    const char* aSlotBase = smc + (size_t)wid * (DEPTH * 1024);
    const unsigned fragOff = (unsigned)(rquad * 64 + (lane & 3) * 16);

#pragma unroll 1
    for (int ks = 0; ks < NKS; ks++) {
        if (ks + DEPTH - 1 < NKS) {
            stageA(ks + DEPTH - 1);
            asm volatile("cp.async.wait_group %0;" :: "n"(DEPTH - 1) : "memory");
        } else {
            asm volatile("cp.async.wait_group 0;" ::: "memory");
        }

        const char* slot = aSlotBase + ((ks & (DEPTH - 1)) << 10);
        float4 v0 = *reinterpret_cast<const float4*>(slot + fragOff);          // rows r0
        float4 v1 = *reinterpret_cast<const float4*>(slot + fragOff + 512);    // rows r1

        uint32_t ah[4], al[4];
        ah[0] = cvt_h2(v0.x, v0.y);  al[0] = cvt_h2_lo(v0.x, v0.y, ah[0]);
        ah[2] = cvt_h2(v0.z, v0.w);  al[2] = cvt_h2_lo(v0.z, v0.w, ah[2]);
        ah[1] = cvt_h2(v1.x, v1.y);  al[1] = cvt_h2_lo(v1.x, v1.y, ah[1]);
        ah[3] = cvt_h2(v1.z, v1.w);  al[3] = cvt_h2_lo(v1.z, v1.w, ah[3]);

        const uint2* bp = sB + ks * (NNT * 32) + lane;
        uint2 fn = bp[0];                  // rotating B prefetch
#pragma unroll
        for (int nt = 0; nt < NNT; nt++) {
            uint2 f = fn;
            if (nt + 1 < NNT) fn = bp[(nt + 1) * 32];
            mma_f16(acc[nt], ah, f.x, f.y);   // hi * hi
            mma_f16(acc[nt], al, f.x, f.y);   // lo * hi
        }
    }
    __syncthreads();   // A ring dead everywhere; sProj/sScores alias it below

    // ---- writeback acc -> sProj[kh][l] ----
#pragma unroll
    for (int nt = 0; nt < NNT; nt++) {
#pragma unroll
        for (int c = 0; c < 4; c++) {
            int row = mrow0 + rquad + ((c >> 1) ? 8 : 0);
            int col = nt * 8 + ((lane & 3) << 1) + (c & 1);
            if (row < L_ && col < 50)
                sProj[col * L_ + row] = acc[nt][c];
        }
    }
    __syncthreads();

    // ---- window-3 attention scores: scores[k][l] ----
    for (int idx = tid; idx < K_ * L_; idx += NT) {
        int k = idx / L_, l = idx - k * L_;
        const float* aEk = sAE + k * 3 * H_;
        const float* pk  = sProj + k * H_ * L_;
        float s = 0.f;
#pragma unroll
        for (int i = 0; i < 3; i++) {
            int ll = l - 1 + i;
            if ((unsigned)ll < (unsigned)L_) {
#pragma unroll
                for (int h = 0; h < H_; h++)
                    s += pk[h * L_ + ll] * aEk[h * 3 + i];
            }
        }
        sScores[idx] = s;
    }
    __syncthreads();

    // ---- softmax over l per k (warp k), write attn out (B,K,L) ----
    if (wid < K_) {
        float* srow = sScores + wid * L_;
        float m = -3.402823466e38f;
        for (int l = lane; l < L_; l += 32) m = fmaxf(m, srow[l]);
#pragma unroll
        for (int o = 16; o > 0; o >>= 1) m = fmaxf(m, __shfl_xor_sync(0xffffffffu, m, o));
        float ssum = 0.f;
        for (int l = lane; l < L_; l += 32) {
            float ev = expf(srow[l] - m);
            srow[l] = ev;
            ssum += ev;
        }
#pragma unroll
        for (int o = 16; o > 0; o >>= 1) ssum += __shfl_xor_sync(0xffffffffu, ssum, o);
        float inv = 1.0f / ssum;
        float* oa = out + (size_t)b * (K_ * L_) + wid * L_;
        for (int l = lane; l < L_; l += 32) {
            float a = srow[l] * inv;
            srow[l] = a;          // keep normalized attn for pooling
            oa[l] = a;
        }
    }
    __syncthreads();

    // ---- pooled rep: rep[k][h] = sum_l proj[kh][l] * attn[k][l]  -> (B,K,H) ----
    float* orep = out + (size_t)B_ * K_ * L_ + (size_t)b * (K_ * H_);
    for (int kh = wid; kh < K_ * H_; kh += (NT / 32)) {
        int k = kh / H_;
        const float* pk = sProj + kh * L_;
        const float* ak = sScores + k * L_;
        float s = 0.f;
        for (int l = lane; l < L_; l += 32) s += pk[l] * ak[l];
#pragma unroll
        for (int o = 16; o > 0; o >>= 1) s += __shfl_xor_sync(0xffffffffu, s, o);
        if (lane == 0) orep[kh] = s;
    }
}

extern "C" void kernel_launch(void* const* d_in, const int* in_sizes, int n_in,
                              void* d_out, int out_size)
{
    const float* review   = (const float*)d_in[0];
    const float* aspProj  = (const float*)d_in[1];
    const float* aspEmbed = (const float*)d_in[2];
    float* out = (float*)d_out;

    cudaFuncSetAttribute(anr_arl_kernel,
                         cudaFuncAttributeMaxDynamicSharedMemorySize, SMEM_BYTES);
    anr_arl_kernel<<<B_, NT, SMEM_BYTES>>>(review, aspProj, aspEmbed, out);
}